// round 13
// baseline (speedup 1.0000x reference)
#include <cuda_runtime.h>
#include <cstdint>

#define B 8
#define C 128
#define H 256
#define W 256
#define HW (H*W)        // 65536
#define HW4 (HW/4)      // 16384

__device__ float g_pooled[B * HW];
__device__ float g_attn[B * HW];

// ---------------------------------------------------------------------------
// poolPair v2: batches b0, b0+1. grid 1024 x 256. NO smem, NO syncthreads.
// Warp layout: 4 float4-pixels x 8 channel-groups (16 ch each).
//   lane = 4*group + pix  -> lanes of a group load 4 consecutive float4 (64B).
// Each thread max-reduces its 16 channels (4x4 MLP batches), then the 8
// groups combine via shfl_xor; lanes 0..3 write the result.
// ---------------------------------------------------------------------------
__global__ void __launch_bounds__(256) pool_pair_kernel(
        const float* __restrict__ x, int b0)
{
    const int tid  = blockIdx.x * 256 + threadIdx.x;
    const int wid  = tid >> 5;             // 0..8191
    const int lane = threadIdx.x & 31;
    const int sub  = lane >> 2;            // channel group 0..7
    const int pw   = lane & 3;             // pixel within warp 0..3
    const int b    = b0 + (wid >> 12);     // wid / 4096
    const int hw4  = (wid & 4095) * 4 + pw;

    const float4* p = reinterpret_cast<const float4*>(x)
                      + ((size_t)b * C + (size_t)sub * 16) * HW4 + hw4;

    float4 m = make_float4(-3.4e38f, -3.4e38f, -3.4e38f, -3.4e38f);
    #pragma unroll
    for (int k = 0; k < 16; k += 4) {
        float4 v0 = p[(size_t)(k + 0) * HW4];
        float4 v1 = p[(size_t)(k + 1) * HW4];
        float4 v2 = p[(size_t)(k + 2) * HW4];
        float4 v3 = p[(size_t)(k + 3) * HW4];
        m.x = fmaxf(fmaxf(m.x, v0.x), fmaxf(v1.x, fmaxf(v2.x, v3.x)));
        m.y = fmaxf(fmaxf(m.y, v0.y), fmaxf(v1.y, fmaxf(v2.y, v3.y)));
        m.z = fmaxf(fmaxf(m.z, v0.z), fmaxf(v1.z, fmaxf(v2.z, v3.z)));
        m.w = fmaxf(fmaxf(m.w, v0.w), fmaxf(v1.w, fmaxf(v2.w, v3.w)));
    }

    // combine the 8 channel groups (stride 4, 8, 16 in lane space)
    #pragma unroll
    for (int off = 4; off < 32; off <<= 1) {
        m.x = fmaxf(m.x, __shfl_xor_sync(0xffffffffu, m.x, off));
        m.y = fmaxf(m.y, __shfl_xor_sync(0xffffffffu, m.y, off));
        m.z = fmaxf(m.z, __shfl_xor_sync(0xffffffffu, m.z, off));
        m.w = fmaxf(m.w, __shfl_xor_sync(0xffffffffu, m.w, off));
    }

    if (sub == 0)
        reinterpret_cast<float4*>(g_pooled)[(size_t)b * HW4 + hw4] = m;
}

// ---------------------------------------------------------------------------
// convPair: batches b0, b0+1. grid (4,16,2), block 256. (R10's version)
// ---------------------------------------------------------------------------
#define TW 64
#define TH 16

__global__ void __launch_bounds__(256) conv_pair_kernel(
        const float* __restrict__ cw, const float* __restrict__ cb, int b0)
{
    __shared__ float s[TH + 6][TW + 8];
    const int b   = b0 + blockIdx.z;
    const int tx0 = blockIdx.x * TW;
    const int ty0 = blockIdx.y * TH;
    const float* pb = g_pooled + b * HW;

    for (int i = threadIdx.x; i < (TH + 6) * (TW + 6); i += 256) {
        int ly = i / (TW + 6);
        int lx = i - ly * (TW + 6);
        int gy = ty0 + ly - 3;
        int gx = tx0 + lx - 3;
        float v = 0.0f;
        if (gy >= 0 && gy < H && gx >= 0 && gx < W) v = pb[gy * W + gx];
        s[ly][lx] = v;
    }
    __syncthreads();

    float wr[49];
    #pragma unroll
    for (int i = 0; i < 49; ++i) wr[i] = __ldg(&cw[i]);
    const float bias = __ldg(&cb[0]);

    const int lx  = threadIdx.x & (TW - 1);
    const int ly0 = threadIdx.x >> 6;

    #pragma unroll
    for (int r = 0; r < TH; r += 4) {
        const int ly = ly0 + r;
        float acc = bias;
        #pragma unroll
        for (int i = 0; i < 7; ++i)
            #pragma unroll
            for (int j = 0; j < 7; ++j)
                acc = fmaf(s[ly + i][lx + j], wr[i * 7 + j], acc);
        float sg = 1.0f / (1.0f + __expf(-acc));
        g_attn[b * HW + (ty0 + ly) * W + tx0 + lx] = sg;
    }
}

// ---------------------------------------------------------------------------
// mulPair: batches b0, b0+1. grid 16384, block 256, one float4 per thread.
// (R10's measured-good version: x reads hit L2 from the pool pass.)
// ---------------------------------------------------------------------------
__global__ void __launch_bounds__(256) mul_pair_kernel(
        const float* __restrict__ x, float* __restrict__ out, int b0)
{
    size_t i = (size_t)blockIdx.x * blockDim.x + threadIdx.x;  // f4 idx in pair
    int hw4 = (int)(i & (HW4 - 1));
    int bi  = (int)(i >> 21);
    size_t gi = ((size_t)(b0 + bi)) * C * HW4 + (i & ((1u << 21) - 1));

    float4 a = __ldg(reinterpret_cast<const float4*>(g_attn)
                     + (size_t)(b0 + bi) * HW4 + hw4);
    float4 v = __ldcs(reinterpret_cast<const float4*>(x) + gi);
    v.x *= a.x; v.y *= a.y; v.z *= a.z; v.w *= a.w;
    __stcs(reinterpret_cast<float4*>(out) + gi, v);
}

// ---------------------------------------------------------------------------
extern "C" void kernel_launch(void* const* d_in, const int* in_sizes, int n_in,
                              void* d_out, int out_size) {
    const float* x  = (const float*)d_in[0];
    const float* cw = (const float*)d_in[1];
    const float* cb = (const float*)d_in[2];
    float* out = (float*)d_out;

    dim3 gc(W / TW, H / TH, 2);
    for (int p = 0; p < 4; ++p) {
        const int b0 = 2 * p;
        pool_pair_kernel<<<1024, 256>>>(x, b0);
        conv_pair_kernel<<<gc, 256>>>(cw, cb, b0);
        mul_pair_kernel<<<2 * C * HW4 / 256, 256>>>(x, out, b0);
    }
}